// round 14
// baseline (speedup 1.0000x reference)
#include <cuda_runtime.h>

#define WI 512
#define HI 512
#define BN 8
#define CN 8
#define HW (HI * WI)
#define TPB 256
#define PXT 2
#define NTHREADS (BN * HW / PXT)     // 1048576
#define NBLK (NTHREADS / TPB)        // 4096

// Accumulators (module-load zeroed; last block resets for graph replay).
__device__ double g_big;
__device__ double g_small;
__device__ unsigned g_ticket;

// sigmoid via single MUFU.TANH: sigma(x) = 0.5*tanh(x/2) + 0.5
__device__ __forceinline__ float sigf(float x) {
    float t;
    asm("tanh.approx.f32 %0, %1;" : "=f"(t) : "f"(0.5f * x));
    return fmaf(0.5f, t, 0.5f);
}
#define CLOG2_MIN (-144.26950408889634f)   // -100 / ln2
__device__ __forceinline__ float clog2f_(float x) {
    return fmaxf(__log2f(x), CLOG2_MIN);
}
__device__ __forceinline__ float2 ld2(const float* p) {
    return __ldg((const float2*)p);
}
__device__ __forceinline__ float2 sig2(float2 f) {
    return make_float2(sigf(f.x), sigf(f.y));
}
// Off-row neighbor probs for the 2-pixel group; OOB -> exactly 0.0
__device__ __forceinline__ float2 nbr2(const float* __restrict__ plane,
                                       int rn, int w0, int dw) {
    if ((unsigned)rn >= (unsigned)HI) return make_float2(0.f, 0.f);
    const float* row = plane + rn * WI;
    if (dw == 0) return sig2(ld2(row + w0));
    int wa = w0 + dw, wb = w0 + 1 + dw;
    float a = ((unsigned)wa < (unsigned)WI) ? sigf(__ldg(row + wa)) : 0.f;
    float b = ((unsigned)wb < (unsigned)WI) ? sigf(__ldg(row + wb)) : 0.f;
    return make_float2(a, b);
}

struct Acc { float prodP, prodV, extra, g1, g2, s, vmin; };

__device__ __forceinline__ void lane_acc(float pa, float pd, float n1, float n2,
                                         float t, Acc& a) {
    float v1 = pa * n1, v2 = pd * n2;
    bool tt = t > 0.5f;                      // binary target
    float fa = tt ? pa : 1.f - pa;
    float fd = tt ? pd : 1.f - pd;
    a.prodP *= fa * fd;
    float f1 = tt ? v1 : 1.f - v1;
    float f2 = tt ? v2 : 1.f - v2;
    // f1 == 0 only at zero-padded borders with t==1, and then f2 == 0 too
    // (same padding geometry): both clamp to -100, weight 0.2 each -> -40.
    if (f1 == 0.f) a.extra += -40.f;
    else           a.prodV *= f1 * f2;
    a.g1 += v1; a.g2 += v2; a.s += t;
    a.vmin = fminf(a.vmin, v2);
}

__global__ void __launch_bounds__(TPB, 4) loss_k(
    const float* __restrict__ atts, const float* __restrict__ dets,
    const float* __restrict__ target, const float* __restrict__ con,
    float* __restrict__ out)
{
    int idx = blockIdx.x * TPB + threadIdx.x;     // [0, NTHREADS)
    int w0 = (idx & (WI / 2 - 1)) * 2;            // 256 pairs per row
    int r  = (idx >> 8) & (HI - 1);
    int b  = idx >> 17;
    int off = r * WI + w0;

    const float* A = atts + (size_t)b * CN * HW;
    const float* D = dets + (size_t)b * CN * HW;
    const float* C = con  + (size_t)b * CN * HW;

    Acc a0 = {1.f, 1.f, 0.f, 0.f, 0.f, 0.f, 2.f};
    Acc a1 = {1.f, 1.f, 0.f, 0.f, 0.f, 0.f, 2.f};

    // Stash planes 3 & 4 centers: they double as same-row neighbors.
    float2 pa3 = sig2(ld2(A + 3 * HW + off));
    float2 pd3 = sig2(ld2(D + 3 * HW + off));
    float2 pa4 = sig2(ld2(A + 4 * HW + off));
    float2 pd4 = sig2(ld2(D + 4 * HW + off));

    {   // ch=3: neighbor plane 4 at (r, w-1): px0 -> edge, px1 -> pa4.x
        float eA = (w0 > 0) ? sigf(__ldg(A + 4 * HW + off - 1)) : 0.f;
        float eD = (w0 > 0) ? sigf(__ldg(D + 4 * HW + off - 1)) : 0.f;
        float2 t2 = ld2(C + 3 * HW + off);
        lane_acc(pa3.x, pd3.x, eA,    eD,    t2.x, a0);
        lane_acc(pa3.y, pd3.y, pa4.x, pd4.x, t2.y, a1);
    }
    {   // ch=4: neighbor plane 3 at (r, w+1): px0 -> pa3.y, px1 -> edge
        float eA = (w0 + 2 < WI) ? sigf(__ldg(A + 3 * HW + off + 2)) : 0.f;
        float eD = (w0 + 2 < WI) ? sigf(__ldg(D + 3 * HW + off + 2)) : 0.f;
        float2 t2 = ld2(C + 4 * HW + off);
        lane_acc(pa4.x, pd4.x, pa3.y, pd3.y, t2.x, a0);
        lane_acc(pa4.y, pd4.y, eA,    eD,    t2.y, a1);
    }

    // Off-row channels: neighbor plane j=7-ch at row r+dr.
    const int chs[6] = { 0,  1,  2,  5, 6, 7 };
    const int drs[6] = {-1, -1, -1,  1, 1, 1 };   // drt[7-ch]
    const int dws[6] = {-1,  0,  1, -1, 0, 1 };   // dwt[7-ch]
#pragma unroll
    for (int k = 0; k < 6; k++) {
        const int ch = chs[k], j = 7 - ch;
        const int rn = r + drs[k];
        float2 n1 = nbr2(A + j * HW, rn, w0, dws[k]);
        float2 n2 = nbr2(D + j * HW, rn, w0, dws[k]);
        float2 pa = sig2(ld2(A + ch * HW + off));
        float2 pd = sig2(ld2(D + ch * HW + off));
        float2 t2 = ld2(C + ch * HW + off);
        lane_acc(pa.x, pd.x, n1.x, n2.x, t2.x, a0);
        lane_acc(pa.y, pd.y, n1.y, n2.y, t2.y, a1);
    }

    // ---- per-pixel finalize (log2 domain) ----
    const float LN2 = 0.69314718055994531f;
    float2 tg = ld2(target + (size_t)b * HW + off);
    float big = 0.f, small2 = 0.f;
    {
        Acc* aa[2] = { &a0, &a1 };
        float tga[2] = { tg.x, tg.y };
#pragma unroll
        for (int i = 0; i < 2; i++) {
            Acc& a = *aa[i];
            big += LN2 * (0.8f * __log2f(a.prodP) + 0.2f * __log2f(a.prodV))
                 + a.extra;
            float g1 = a.g1 * 0.125f;                   // glo_map1
            float g2 = a.g2 * 0.125f;                   // glo_map2
            bool tt = tga[i] > 0.5f;
            float sm2 = clog2f_(tt ? g1 : 1.f - g1);    // bce_loss1
            bool edge = (a.s > 0.5f) && (a.s < 7.5f);   // 0 < sum(con) < 8
            float dec = edge ? (1.f - a.vmin) : g2;     // decouple_map
            sm2 += clog2f_(tt ? dec : 1.f - dec);       // de_loss2
            small2 += sm2;
        }
    }
    float small = LN2 * small2;

    // ---- block reduction (two floats) ----
#pragma unroll
    for (int o = 16; o > 0; o >>= 1) {
        big   += __shfl_down_sync(0xffffffffu, big, o);
        small += __shfl_down_sync(0xffffffffu, small, o);
    }
    __shared__ float sb[8], ss[8];
    int lane = threadIdx.x & 31;
    int wid  = threadIdx.x >> 5;
    if (lane == 0) { sb[wid] = big; ss[wid] = small; }
    __syncthreads();
    if (wid == 0) {
        big   = (lane < 8) ? sb[lane] : 0.f;
        small = (lane < 8) ? ss[lane] : 0.f;
#pragma unroll
        for (int o = 4; o > 0; o >>= 1) {
            big   += __shfl_down_sync(0xffffffffu, big, o);
            small += __shfl_down_sync(0xffffffffu, small, o);
        }
        if (lane == 0) {
            atomicAdd(&g_big,   (double)big);
            atomicAdd(&g_small, (double)small);
            __threadfence();
            unsigned t = atomicAdd(&g_ticket, 1u);
            if (t == (unsigned)(NBLK - 1)) {
                double B = atomicAdd(&g_big,   0.0);
                double S = atomicAdd(&g_small, 0.0);
                const double N8 = (double)BN * CN * HW;  // 16777216
                const double N1 = (double)BN * HW;       // 2097152
                out[0] = (float)(-(B / N8) - (S / N1));
                g_big = 0.0;
                g_small = 0.0;
                __threadfence();
                g_ticket = 0u;
            }
        }
    }
}

extern "C" void kernel_launch(void* const* d_in, const int* in_sizes, int n_in,
                              void* d_out, int out_size) {
    const float* atts   = (const float*)d_in[0];
    const float* dets   = (const float*)d_in[1];
    const float* target = (const float*)d_in[2];
    const float* con    = (const float*)d_in[3];
    float* out = (float*)d_out;

    loss_k<<<NBLK, TPB>>>(atts, dets, target, con, out);
}